// round 3
// baseline (speedup 1.0000x reference)
#include <cuda_runtime.h>
#include <cstdint>
#include <math.h>

#define HW    128
#define NPIX  (HW*HW)        // 16384
#define NBATCH 16

// Scratch (allocation-free rule: __device__ globals)
__device__ int g_SAT[NPIX];   // inclusive 2D prefix sum of template
__device__ int g_C[NPIX];     // per-pixel template weight map (integer)

// ---------------------------------------------------------------------------
// Kernel 1: build SAT of hex template, derive weight map C, zero the output.
// Single block of 128 threads; global memory + __syncthreads (block-coherent).
// ---------------------------------------------------------------------------
__global__ void prep_kernel(const float* __restrict__ tmpl, float* __restrict__ out) {
    int t = threadIdx.x;   // 0..127
    if (t == 0) *out = 0.0f;

    // phase 1: row-wise prefix (thread t owns row t)
    {
        int run = 0;
        const float* row = tmpl + t * HW;
        int* srow = g_SAT + t * HW;
        #pragma unroll 4
        for (int x = 0; x < HW; ++x) {
            run += (row[x] > 0.5f) ? 1 : 0;
            srow[x] = run;
        }
    }
    __syncthreads();
    // phase 2: column-wise prefix (thread t owns column t)
    {
        int run = 0;
        #pragma unroll 4
        for (int y = 0; y < HW; ++y) {
            run += g_SAT[y * HW + t];
            g_SAT[y * HW + t] = run;
        }
    }
    __syncthreads();
    // phase 3: weight map. Contribution window of pixel p into SAME conv with
    // k=128 (pad_low=63, pad_high=64, cross-correlation):
    //   C[p] = sum of tmpl over rows [py-64, py+63], cols [px-64, px+63] (clipped)
    for (int p = t; p < NPIX; p += blockDim.x) {
        int py = p >> 7, px = p & 127;
        int y0 = py - 64; if (y0 < 0) y0 = 0;
        int y1 = py + 63; if (y1 > 127) y1 = 127;
        int x0 = px - 64; if (x0 < 0) x0 = 0;
        int x1 = px + 63; if (x1 > 127) x1 = 127;
        int s = g_SAT[y1 * HW + x1];
        if (y0 > 0)           s -= g_SAT[(y0 - 1) * HW + x1];
        if (x0 > 0)           s -= g_SAT[y1 * HW + (x0 - 1)];
        if (y0 > 0 && x0 > 0) s += g_SAT[(y0 - 1) * HW + (x0 - 1)];
        g_C[p] = s;
    }
}

// ---------------------------------------------------------------------------
// Union-find helpers (shared-memory, lock-free atomicMin union).
// Labels only decrease and always point to smaller indices -> no cycles.
// ---------------------------------------------------------------------------
__device__ __forceinline__ unsigned find_root(unsigned* lab, unsigned a) {
    volatile unsigned* v = (volatile unsigned*)lab;
    unsigned n = v[a];
    while (n != a) { a = n; n = v[a]; }
    return n;
}

__device__ __forceinline__ void merge_lab(unsigned* lab, unsigned a, unsigned b) {
    for (;;) {
        a = find_root(lab, a);
        b = find_root(lab, b);
        if (a == b) return;
        if (a > b) { unsigned t = a; a = b; b = t; }
        unsigned old = atomicMin(&lab[b], a);
        if (old == b) return;
        b = old;
    }
}

__device__ __forceinline__ int getbit(const unsigned* bits, int y, int x) {
    if ((unsigned)y >= (unsigned)HW || (unsigned)x >= (unsigned)HW) return 0;
    return (bits[(y << 2) | (x >> 5)] >> (x & 31)) & 1;
}

// ---------------------------------------------------------------------------
// Kernel 2: one CTA per batch sample.
// Dynamic smem: lab[16384] u32 (64KB) + bits[512] u32 (2KB) = 67584 B.
// ---------------------------------------------------------------------------
__global__ void __launch_bounds__(1024, 1)
hex_loss_kernel(const float* __restrict__ preds, float* __restrict__ out) {
    extern __shared__ unsigned smem_u[];
    unsigned* lab  = smem_u;           // NPIX entries
    unsigned* bits = smem_u + NPIX;    // NPIX/32 = 512 entries

    __shared__ int s_area, s_perim, s_tsum, s_ncomp;

    const int tid = threadIdx.x;
    const int b   = blockIdx.x;
    const float* src = preds + b * NPIX;

    if (tid == 0) { s_area = 0; s_perim = 0; s_tsum = 0; s_ncomp = 0; }
    __syncthreads();

    // ---- binarize (coalesced), pack bitset, init labels, area + template sum
    int myArea = 0, myT = 0;
    #pragma unroll
    for (int it = 0; it < NPIX / 1024; ++it) {
        int p = it * 1024 + tid;
        int v = (src[p] > 0.5f) ? 1 : 0;
        unsigned ball = __ballot_sync(0xFFFFFFFFu, v);
        if ((tid & 31) == 0) bits[p >> 5] = ball;
        myArea += v;
        if (v) myT += g_C[p];
        lab[p] = v ? (unsigned)p : 0xFFFFFFFFu;
    }
    atomicAdd(&s_area, myArea);
    atomicAdd(&s_tsum, myT);
    __syncthreads();

    // ---- Sobel perimeter: edges>0.5 <=> gx!=0 || gy!=0 (binary/integer image)
    int myP = 0;
    #pragma unroll
    for (int it = 0; it < NPIX / 1024; ++it) {
        int p = it * 1024 + tid;
        int y = p >> 7, x = p & 127;
        int tl = getbit(bits, y - 1, x - 1), tc = getbit(bits, y - 1, x), tr = getbit(bits, y - 1, x + 1);
        int lf = getbit(bits, y,     x - 1),                              rt = getbit(bits, y,     x + 1);
        int bl = getbit(bits, y + 1, x - 1), bc = getbit(bits, y + 1, x), br = getbit(bits, y + 1, x + 1);
        int gx = (tr + 2 * rt + br) - (tl + 2 * lf + bl);
        int gy = (bl + 2 * bc + br) - (tl + 2 * tc + tr);
        myP += ((gx != 0) | (gy != 0));
    }
    atomicAdd(&s_perim, myP);

    // ---- single-pass union-find over right/down edges (lab & bits are synced)
    for (int it = 0; it < NPIX / 1024; ++it) {
        int p = it * 1024 + tid;
        unsigned w = bits[p >> 5];
        if (!((w >> (p & 31)) & 1)) continue;
        int y = p >> 7, x = p & 127;
        if (x < HW - 1 && ((bits[(p + 1) >> 5] >> ((p + 1) & 31)) & 1))
            merge_lab(lab, (unsigned)p, (unsigned)(p + 1));
        if (y < HW - 1 && ((bits[(p + HW) >> 5] >> ((p + HW) & 31)) & 1))
            merge_lab(lab, (unsigned)p, (unsigned)(p + HW));
    }
    __syncthreads();

    // ---- count roots (component minima): lab[p] == p (bg is 0xFFFFFFFF != p)
    int myC = 0;
    #pragma unroll
    for (int it = 0; it < NPIX / 1024; ++it) {
        int p = it * 1024 + tid;
        myC += (lab[p] == (unsigned)p);
    }
    atomicAdd(&s_ncomp, myC);
    __syncthreads();

    // ---- per-sample loss
    if (tid == 0) {
        float area = (float)s_area;
        float per  = (float)s_perim;
        float comp = per * per / (area + 1e-6f);
        float geom = (s_area == 0) ? 0.0f : fabsf(comp - 4.51f);
        float tmplL = 1.0f - (float)s_tsum * (1.0f / (float)NPIX);
        int mc = s_ncomp - 1; if (mc < 0) mc = 0;
        float sample = (float)mc + geom + tmplL;
        atomicAdd(out, sample * (1.0f / (float)NBATCH));
    }
}

// ---------------------------------------------------------------------------
extern "C" void kernel_launch(void* const* d_in, const int* in_sizes, int n_in,
                              void* d_out, int out_size) {
    const float* preds = (const float*)d_in[0];       // [16,1,128,128]
    const float* tmpl  = (const float*)d_in[1];       // [1,1,128,128]
    float* out = (float*)d_out;                       // scalar

    static const size_t SMEM = (NPIX + NPIX / 32) * sizeof(unsigned); // 67584
    cudaFuncSetAttribute(hex_loss_kernel,
                         cudaFuncAttributeMaxDynamicSharedMemorySize, (int)SMEM);

    prep_kernel<<<1, 128>>>(tmpl, out);
    hex_loss_kernel<<<NBATCH, 1024, SMEM>>>(preds, out);
}

// round 8
// speedup vs baseline: 3.8571x; 3.8571x over previous
#include <cuda_runtime.h>
#include <math.h>

#define HW     128
#define NPIX   (HW*HW)     // 16384
#define NBATCH 16

__device__ float g_partial[NBATCH];

// ---------------------------------------------------------------------------
// Lock-free union-find on shared memory, union-by-min-index + path halving.
// Parents only ever decrease and always point to ancestors -> races benign.
// ---------------------------------------------------------------------------
__device__ __forceinline__ unsigned find_root(unsigned* lab, unsigned a) {
    volatile unsigned* v = (volatile unsigned*)lab;
    for (;;) {
        unsigned n = v[a];
        if (n == a) return a;
        unsigned gp = v[n];
        if (gp == n) return n;
        v[a] = gp;            // path halving
        a = gp;
    }
}

__device__ __forceinline__ void merge_lab(unsigned* lab, unsigned a, unsigned b) {
    for (;;) {
        a = find_root(lab, a);
        b = find_root(lab, b);
        if (a == b) return;
        if (a > b) { unsigned t = a; a = b; b = t; }
        unsigned old = atomicMin(&lab[b], a);
        if (old == b) return;
        b = old;              // someone else linked b lower; retry from there
    }
}

__device__ __forceinline__ int getbit(const unsigned* bits, int y, int x) {
    if ((unsigned)y >= (unsigned)HW || (unsigned)x >= (unsigned)HW) return 0;
    return (bits[(y << 2) | (x >> 5)] >> (x & 31)) & 1;
}

// ---------------------------------------------------------------------------
// Fused kernel: one CTA per batch sample.
// Dyn smem: buf[16384] u32 (SAT first, then labels) + bits[512] u32 = 67584 B.
// ---------------------------------------------------------------------------
__global__ void __launch_bounds__(1024, 1)
hex_fused_kernel(const float* __restrict__ preds, const float* __restrict__ tmpl) {
    extern __shared__ unsigned sm[];
    unsigned* buf  = sm;          // 16384 entries: template SAT, then labels
    unsigned* bits = sm + NPIX;   // 512 entries: packed bitset (tmpl, then mask)
    int* SAT = (int*)buf;

    __shared__ int s_area, s_perim, s_tsum, s_ncomp;

    const int tid = threadIdx.x;
    const int b   = blockIdx.x;

    if (tid == 0) { s_area = 0; s_perim = 0; s_tsum = 0; s_ncomp = 0; }

    // ---- pack template into bitset (coalesced global reads)
    #pragma unroll
    for (int it = 0; it < NPIX / 1024; ++it) {
        int p = it * 1024 + tid;
        unsigned ball = __ballot_sync(0xFFFFFFFFu, tmpl[p] > 0.5f);
        if ((tid & 31) == 0) bits[p >> 5] = ball;
    }
    __syncthreads();

    // ---- SAT row pass (thread t owns row t, reads smem bits)
    if (tid < HW) {
        int run = 0;
        const unsigned* row = bits + (tid << 2);
        int* srow = SAT + tid * HW;
        #pragma unroll 8
        for (int x = 0; x < HW; ++x) {
            run += (row[x >> 5] >> (x & 31)) & 1;
            srow[x] = run;
        }
    }
    __syncthreads();
    // ---- SAT column pass (thread t owns column t; conflict-free: bank = t&31)
    if (tid < HW) {
        int run = 0;
        #pragma unroll 8
        for (int y = 0; y < HW; ++y) {
            run += SAT[y * HW + tid];
            SAT[y * HW + tid] = run;
        }
    }
    __syncthreads();

    // ---- binarize preds (coalesced), pack mask bitset, area + template sum.
    // C[p] = SAT box sum over rows [py-64,py+63], cols [px-64,px+63] (clipped).
    const float* src = preds + b * NPIX;
    int myA = 0, myT = 0;
    #pragma unroll
    for (int it = 0; it < NPIX / 1024; ++it) {
        int p = it * 1024 + tid;
        int v = (src[p] > 0.5f) ? 1 : 0;
        unsigned ball = __ballot_sync(0xFFFFFFFFu, v);
        if ((tid & 31) == 0) bits[p >> 5] = ball;   // overwrites tmpl bits (done with them after SAT)
        if (v) {
            myA++;
            int py = p >> 7, px = p & 127;
            int y0 = py - 64; if (y0 < 0) y0 = 0;
            int y1 = py + 63; if (y1 > 127) y1 = 127;
            int x0 = px - 64; if (x0 < 0) x0 = 0;
            int x1 = px + 63; if (x1 > 127) x1 = 127;
            int s = SAT[y1 * HW + x1];
            if (y0 > 0)           s -= SAT[(y0 - 1) * HW + x1];
            if (x0 > 0)           s -= SAT[y1 * HW + (x0 - 1)];
            if (y0 > 0 && x0 > 0) s += SAT[(y0 - 1) * HW + (x0 - 1)];
            myT += s;
        }
    }
    #pragma unroll
    for (int o = 16; o; o >>= 1) {
        myA += __shfl_down_sync(0xFFFFFFFFu, myA, o);
        myT += __shfl_down_sync(0xFFFFFFFFu, myT, o);
    }
    if ((tid & 31) == 0) { atomicAdd(&s_area, myA); atomicAdd(&s_tsum, myT); }
    __syncthreads();   // mask bits complete; SAT no longer needed

    // ---- init labels with horizontal run-start (depth-1 trees, no h-merges)
    //      + Sobel perimeter (edges>0.5 <=> gx!=0 || gy!=0 on binary image)
    int myP = 0;
    #pragma unroll
    for (int it = 0; it < NPIX / 1024; ++it) {
        int p = it * 1024 + tid;
        int y = p >> 7, x = p & 127;
        const unsigned* row = bits + (y << 2);
        int v = (row[x >> 5] >> (x & 31)) & 1;

        unsigned labv = 0xFFFFFFFFu;
        if (v) {
            int k = x >> 5, j = x & 31;
            unsigned z = ~row[k] & (j ? ((1u << j) - 1u) : 0u);  // zeros strictly below j
            int start = -1;
            if (z) start = (k << 5) + (32 - __clz(z));
            else {
                for (int kk = k - 1; kk >= 0; --kk) {
                    unsigned zz = ~row[kk];
                    if (zz) { start = (kk << 5) + (32 - __clz(zz)); break; }
                }
                if (start < 0) start = 0;
            }
            labv = (unsigned)(y * HW + start);
        }

        int tl = getbit(bits, y - 1, x - 1), tc = getbit(bits, y - 1, x), tr = getbit(bits, y - 1, x + 1);
        int lf = getbit(bits, y,     x - 1),                              rt = getbit(bits, y,     x + 1);
        int bl = getbit(bits, y + 1, x - 1), bc = getbit(bits, y + 1, x), br = getbit(bits, y + 1, x + 1);
        int gx = (tr + 2 * rt + br) - (tl + 2 * lf + bl);
        int gy = (bl + 2 * bc + br) - (tl + 2 * tc + tr);
        myP += ((gx != 0) | (gy != 0));

        buf[p] = labv;   // overwrites SAT
    }
    #pragma unroll
    for (int o = 16; o; o >>= 1) myP += __shfl_down_sync(0xFFFFFFFFu, myP, o);
    if ((tid & 31) == 0) atomicAdd(&s_perim, myP);
    __syncthreads();

    // ---- vertical merges: one merge per overlapping run pair
    #pragma unroll
    for (int it = 0; it < NPIX / 1024; ++it) {
        int p = it * 1024 + tid;
        int y = p >> 7, x = p & 127;
        if (y == 0) continue;
        if (!getbit(bits, y, x))     continue;
        if (!getbit(bits, y - 1, x)) continue;
        // skip if the edge at x-1 already connects the same two runs
        if (x > 0 && getbit(bits, y, x - 1) && getbit(bits, y - 1, x - 1)) continue;
        merge_lab(buf, (unsigned)p, (unsigned)(p - HW));
    }
    __syncthreads();

    // ---- count roots (component minima): lab[p]==p (bg sentinel never matches)
    int myC = 0;
    #pragma unroll
    for (int it = 0; it < NPIX / 1024; ++it) {
        int p = it * 1024 + tid;
        myC += (buf[p] == (unsigned)p);
    }
    #pragma unroll
    for (int o = 16; o; o >>= 1) myC += __shfl_down_sync(0xFFFFFFFFu, myC, o);
    if ((tid & 31) == 0) atomicAdd(&s_ncomp, myC);
    __syncthreads();

    // ---- per-sample loss
    if (tid == 0) {
        float area = (float)s_area;
        float per  = (float)s_perim;
        float comp = per * per / (area + 1e-6f);
        float geom = (s_area == 0) ? 0.0f : fabsf(comp - 4.51f);
        float tmplL = 1.0f - (float)s_tsum * (1.0f / (float)NPIX);
        int mc = s_ncomp - 1; if (mc < 0) mc = 0;
        g_partial[b] = (float)mc + geom + tmplL;
    }
}

// ---------------------------------------------------------------------------
__global__ void finalize_kernel(float* __restrict__ out) {
    if (threadIdx.x == 0) {
        float s = 0.0f;
        #pragma unroll
        for (int i = 0; i < NBATCH; ++i) s += g_partial[i];
        *out = s * (1.0f / (float)NBATCH);
    }
}

// ---------------------------------------------------------------------------
extern "C" void kernel_launch(void* const* d_in, const int* in_sizes, int n_in,
                              void* d_out, int out_size) {
    const float* preds = (const float*)d_in[0];   // [16,1,128,128]
    const float* tmpl  = (const float*)d_in[1];   // [1,1,128,128]
    float* out = (float*)d_out;

    static const size_t SMEM = (NPIX + NPIX / 32) * sizeof(unsigned); // 67584
    cudaFuncSetAttribute(hex_fused_kernel,
                         cudaFuncAttributeMaxDynamicSharedMemorySize, (int)SMEM);

    hex_fused_kernel<<<NBATCH, 1024, SMEM>>>(preds, tmpl);
    finalize_kernel<<<1, 32>>>(out);
}

// round 15
// speedup vs baseline: 10.1210x; 2.6240x over previous
#include <cuda_runtime.h>
#include <math.h>

#define HW     128
#define NPIX   (HW*HW)     // 16384
#define NWORD  (NPIX/32)   // 512
#define NBATCH 16

__device__ float    g_partial[NBATCH];
__device__ unsigned g_counter = 0;

// ---------------------------------------------------------------------------
// Lock-free union-find, union-by-min-index + path halving.
// Parents only decrease and always point to ancestors -> acyclic, races benign.
// merge_link returns 1 iff it installed a link (lab[b] transitioned b -> a),
// which happens exactly once per root that stops being a root, so
//   #components = #runs - #successful links.
// ---------------------------------------------------------------------------
__device__ __forceinline__ unsigned find_root(unsigned* lab, unsigned a) {
    volatile unsigned* v = (volatile unsigned*)lab;
    for (;;) {
        unsigned n = v[a];
        if (n == a) return a;
        unsigned gp = v[n];
        if (gp == n) return n;
        v[a] = gp;            // path halving
        a = gp;
    }
}

__device__ __forceinline__ int merge_link(unsigned* lab, unsigned a, unsigned b) {
    a = find_root(lab, a);
    b = find_root(lab, b);
    for (;;) {
        if (a == b) return 0;
        if (a > b) { unsigned t = a; a = b; b = t; }
        unsigned old = atomicMin(&lab[b], a);
        if (old == b) return 1;          // we uniquely retired root b
        b = find_root(lab, old);
        a = find_root(lab, a);
    }
}

// ---------------------------------------------------------------------------
// One CTA per batch sample. Dynamic smem (u32):
//   buf[16384] : template SAT, then union-find labels (only run-starts used)
//   mbits[512] : packed binarized mask
//   tbits[512] : packed template bits (dead after SAT row pass)
//   rs[512]    : run-start bits (written after segsum staging is dead)
//   segsum aliases the tbits+rs region during the SAT column pass.
// ---------------------------------------------------------------------------
__global__ void __launch_bounds__(1024, 1)
hex_fused_kernel(const float* __restrict__ preds, const float* __restrict__ tmpl,
                 float* __restrict__ out) {
    extern __shared__ unsigned sm[];
    unsigned* buf    = sm;                 // 16384
    unsigned* mbits  = sm + NPIX;          // 512
    unsigned* tbits  = sm + NPIX + 512;    // 512
    unsigned* rs     = sm + NPIX + 1024;   // 512
    unsigned* segsum = tbits;              // 1024 u32 staging (aliases tbits+rs)
    int* SAT = (int*)buf;

    __shared__ int s_area, s_perim, s_tsum, s_runs, s_links;

    const int tid = threadIdx.x;
    const int b   = blockIdx.x;

    if (tid == 0) { s_area = 0; s_perim = 0; s_tsum = 0; s_runs = 0; s_links = 0; }

    // ---- phase 1: binarize preds -> mbits ; pack template -> tbits
    const float* src = preds + b * NPIX;
    #pragma unroll
    for (int it = 0; it < NPIX / 1024; ++it) {
        int p = it * 1024 + tid;
        unsigned bm = __ballot_sync(0xFFFFFFFFu, src[p] > 0.5f);
        if ((tid & 31) == 0) mbits[p >> 5] = bm;
    }
    #pragma unroll
    for (int it = 0; it < NPIX / 1024; ++it) {
        int p = it * 1024 + tid;
        unsigned bt = __ballot_sync(0xFFFFFFFFu, tmpl[p] > 0.5f);
        if ((tid & 31) == 0) tbits[p >> 5] = bt;
    }
    __syncthreads();

    // ---- phase 2a: SAT row pass. thread -> (row r, 16-col segment s)
    {
        int r = tid >> 3, s = tid & 7;
        unsigned hw16 = (tbits[(r << 2) + (s >> 1)] >> ((s & 1) * 16)) & 0xFFFFu;
        int seg = __popc(hw16);
        int incl = seg;                      // 8-lane inclusive scan
        #pragma unroll
        for (int d = 1; d < 8; d <<= 1) {
            int v = __shfl_up_sync(0xFFFFFFFFu, incl, d, 8);
            if (s >= d) incl += v;
        }
        int run = incl - seg;                // exclusive base
        int* srow = SAT + r * HW + s * 16;
        #pragma unroll
        for (int i = 0; i < 16; ++i) {
            run += (hw16 >> i) & 1;
            srow[i] = run;
        }
    }
    __syncthreads();
    // ---- phase 2b: SAT column pass, segmented. thread -> (col c, 16-row seg s2)
    {
        int c = tid & 127, s2 = tid >> 7;
        int y0 = s2 * 16;
        int vals[16], tot = 0;
        #pragma unroll
        for (int i = 0; i < 16; ++i) { vals[i] = SAT[(y0 + i) * HW + c]; tot += vals[i]; }
        segsum[s2 * 128 + c] = (unsigned)tot;
        __syncthreads();
        int base = 0;
        for (int s3 = 0; s3 < s2; ++s3) base += (int)segsum[s3 * 128 + c];
        int run = base;
        #pragma unroll
        for (int i = 0; i < 16; ++i) {
            run += vals[i];
            SAT[(y0 + i) * HW + c] = run;
        }
    }
    __syncthreads();

    // ---- phase 3: template-match sum. C[p] = SAT box [py-64,py+63]x[px-64,px+63]
    {
        int myT = 0;
        #pragma unroll
        for (int it = 0; it < NPIX / 1024; ++it) {
            int p = it * 1024 + tid;
            if ((mbits[p >> 5] >> (p & 31)) & 1) {
                int py = p >> 7, px = p & 127;
                int y0 = py - 64; if (y0 < 0) y0 = 0;
                int y1 = py + 63; if (y1 > 127) y1 = 127;
                int x0 = px - 64; if (x0 < 0) x0 = 0;
                int x1 = px + 63; if (x1 > 127) x1 = 127;
                int s = SAT[y1 * HW + x1];
                if (y0 > 0)           s -= SAT[(y0 - 1) * HW + x1];
                if (x0 > 0)           s -= SAT[y1 * HW + (x0 - 1)];
                if (y0 > 0 && x0 > 0) s += SAT[(y0 - 1) * HW + (x0 - 1)];
                myT += s;
            }
        }
        #pragma unroll
        for (int o = 16; o; o >>= 1) myT += __shfl_down_sync(0xFFFFFFFFu, myT, o);
        if ((tid & 31) == 0) atomicAdd(&s_tsum, myT);
    }
    __syncthreads();   // SAT dead; buf becomes label array

    // ---- phase 4: run-start bits + label init + run count, bit-parallel
    //      Sobel perimeter + area. One packed word per thread (tid<512).
    {
        int myR = 0, myP = 0, myA = 0;
        if (tid < NWORD) {
            int w = tid, y = w >> 2, k = w & 3;
            unsigned ww = mbits[w];

            unsigned carry = (k > 0) ? (mbits[w - 1] >> 31) : 0u;
            unsigned rsw = ww & ~((ww << 1) | carry);
            rs[w] = rsw;
            myR = __popc(rsw);
            unsigned t = rsw;
            while (t) {
                unsigned bbit = t & (0u - t);
                int j = __popc(bbit - 1u);
                buf[(w << 5) + j] = (unsigned)((w << 5) + j);
                t ^= bbit;
            }

            // 8 neighbor bit-planes (0 outside image)
            unsigned u  = (y > 0)   ? mbits[w - 4] : 0u;
            unsigned d  = (y < 127) ? mbits[w + 4] : 0u;
            unsigned cl = (k > 0) ? mbits[w - 1] : 0u, cr = (k < 3) ? mbits[w + 1] : 0u;
            unsigned ul = (y > 0 && k > 0) ? mbits[w - 5] : 0u, ur = (y > 0 && k < 3) ? mbits[w - 3] : 0u;
            unsigned dl = (y < 127 && k > 0) ? mbits[w + 3] : 0u, dr = (y < 127 && k < 3) ? mbits[w + 5] : 0u;
            unsigned tl = (u << 1) | (ul >> 31), tr = (u >> 1) | (ur << 31);
            unsigned lf = (ww << 1) | (cl >> 31), rt = (ww >> 1) | (cr << 31);
            unsigned bl = (d << 1) | (dl >> 31), br = (d >> 1) | (dr << 31);
            // gx != 0  <=>  (tl + bl + 2*lf) != (tr + br + 2*rt), 3-bit slices
            unsigned a0 = tl ^ bl, ac = tl & bl, a1 = ac ^ lf, a2 = ac & lf;
            unsigned b0 = tr ^ br, bc = tr & br, b1 = bc ^ rt, b2 = bc & rt;
            unsigned gxnz = (a0 ^ b0) | (a1 ^ b1) | (a2 ^ b2);
            // gy != 0  <=>  (tl + tr + 2*tc) != (bl + br + 2*bc)
            unsigned c0 = tl ^ tr, cc = tl & tr, c1 = cc ^ u, c2 = cc & u;
            unsigned d0 = bl ^ br, dc = bl & br, d1 = dc ^ d, d2 = dc & d;
            unsigned gynz = (c0 ^ d0) | (c1 ^ d1) | (c2 ^ d2);

            myP = __popc(gxnz | gynz);
            myA = __popc(ww);
        }
        // unconditional full-warp reductions (inactive warps contribute 0)
        #pragma unroll
        for (int o = 16; o; o >>= 1) {
            myR += __shfl_down_sync(0xFFFFFFFFu, myR, o);
            myP += __shfl_down_sync(0xFFFFFFFFu, myP, o);
            myA += __shfl_down_sync(0xFFFFFFFFu, myA, o);
        }
        if ((tid & 31) == 0 && tid < NWORD) {
            atomicAdd(&s_runs, myR);
            atomicAdd(&s_perim, myP);
            atomicAdd(&s_area, myA);
        }
    }
    __syncthreads();

    // ---- phase 5: vertical merges, one per overlapping run pair.
    // candidate bit = leftmost column of each overlap interval (rows y, y-1).
    {
        int myS = 0;
        if (tid < NWORD - 4) {           // words of rows 1..127
            int w = tid + 4;
            int y = w >> 2, k = w & 3;
            unsigned o = mbits[w] & mbits[w - 4];
            unsigned carry = (k > 0) ? ((mbits[w - 1] & mbits[w - 5]) >> 31) : 0u;
            unsigned cand = o & ~((o << 1) | carry);
            while (cand) {
                unsigned bbit = cand & (0u - cand);
                int j = __popc(bbit - 1u);
                cand ^= bbit;
                int x = (k << 5) + j;
                unsigned pa, pb;
                {   // run start of (y, x)
                    int kk = x >> 5;
                    unsigned m = rs[(y << 2) + kk] & (0xFFFFFFFFu >> (31 - (x & 31)));
                    while (!m) { --kk; m = rs[(y << 2) + kk]; }
                    pa = (unsigned)((y << 7) + (kk << 5) + 31 - __clz(m));
                }
                {   // run start of (y-1, x)
                    int kk = x >> 5, ym = y - 1;
                    unsigned m = rs[(ym << 2) + kk] & (0xFFFFFFFFu >> (31 - (x & 31)));
                    while (!m) { --kk; m = rs[(ym << 2) + kk]; }
                    pb = (unsigned)((ym << 7) + (kk << 5) + 31 - __clz(m));
                }
                myS += merge_link(buf, pa, pb);
            }
        }
        // unconditional full-warp reduction — fixes the R9 hang
        #pragma unroll
        for (int o2 = 16; o2; o2 >>= 1) myS += __shfl_down_sync(0xFFFFFFFFu, myS, o2);
        if ((tid & 31) == 0) atomicAdd(&s_links, myS);
    }
    __syncthreads();

    // ---- phase 6: per-sample loss; last CTA reduces in fixed order
    if (tid == 0) {
        float area = (float)s_area;
        float per  = (float)s_perim;
        float comp = per * per / (area + 1e-6f);
        float geom = (s_area == 0) ? 0.0f : fabsf(comp - 4.51f);
        float tmplL = 1.0f - (float)s_tsum * (1.0f / (float)NPIX);
        int ncomp = s_runs - s_links;
        int mc = ncomp - 1; if (mc < 0) mc = 0;
        g_partial[b] = (float)mc + geom + tmplL;

        __threadfence();
        unsigned ticket = atomicAdd(&g_counter, 1u);
        if (ticket == NBATCH - 1) {
            float s = 0.0f;
            #pragma unroll
            for (int i = 0; i < NBATCH; ++i) s += g_partial[i];
            *out = s * (1.0f / (float)NBATCH);
            g_counter = 0;   // reset for next graph replay
        }
    }
}

// ---------------------------------------------------------------------------
extern "C" void kernel_launch(void* const* d_in, const int* in_sizes, int n_in,
                              void* d_out, int out_size) {
    const float* preds = (const float*)d_in[0];   // [16,1,128,128]
    const float* tmpl  = (const float*)d_in[1];   // [1,1,128,128]
    float* out = (float*)d_out;

    static const size_t SMEM = (NPIX + 3 * 512) * sizeof(unsigned); // 71680
    cudaFuncSetAttribute(hex_fused_kernel,
                         cudaFuncAttributeMaxDynamicSharedMemorySize, (int)SMEM);

    hex_fused_kernel<<<NBATCH, 1024, SMEM>>>(preds, tmpl, out);
}